// round 6
// baseline (speedup 1.0000x reference)
#include <cuda_runtime.h>
#include <math.h>

// Problem constants (fixed shapes from reference)
#define HH 224
#define WW 224
#define CC 3
#define LL 256            // B*F = 8*32
#define NOISE_LEN 766     // 3L-2
#define WIN 511           // 2L-1
#define FRAME_FLOATS (HH * WW * CC)   // 150528
#define FRAME_F2 (FRAME_FLOATS / 2)   // 75264

// Per-frame 3x3 matrices (row-major), produced by kernel 1, consumed by kernel 2.
__device__ float g_M[LL * 9];

// ---------------------------------------------------------------------------
// Kernel 1: fused smoothing + matrix assembly. 128 blocks x 256 threads,
// TWO frames per block (warps 0-3: frame 2b, warps 4-7: frame 2b+1) so the
// whole thing is a single wave on 148 SMs. fp32 window via binary
// exponentiation; fp64 only for the tiny 3x3 assembly.
// ---------------------------------------------------------------------------
__global__ __launch_bounds__(256) void vrp_matrices(const float* __restrict__ noise,
                                                    const float* __restrict__ basis) {
    __shared__ float w[WIN];
    __shared__ float wv_sh[2][4];
    __shared__ double vmax[2][4];
    __shared__ double wp_sh[2][9];
    __shared__ float wsum_sh;

    const int tid = threadIdx.x;

    // Binary powers of 1.1: sq[b] = 1.1^(2^b)
    float sq[8];
    sq[0] = 1.1f;
    #pragma unroll
    for (int b = 1; b < 8; ++b) sq[b] = sq[b - 1] * sq[b - 1];

    // Window: w[t] = 1.1^e, e = t for t<256 else 510-t
    for (int t = tid; t < WIN; t += 256) {
        const int e = (t < LL) ? t : (2 * LL - 2 - t);
        float p = 1.0f;
        #pragma unroll
        for (int b = 0; b < 8; ++b)
            if ((e >> b) & 1) p *= sq[b];
        w[t] = p;
    }
    __syncthreads();

    const int warp = tid >> 5;
    const int lane = tid & 31;
    const int half = warp >> 2;                    // 0 or 1 (which frame)
    const int row  = warp & 3;                     // noise row
    const int frame = blockIdx.x * 2 + half;

    const float* nr = noise + row * NOISE_LEN + frame;
    float dot = 0.f, wsum = 0.f;
    for (int k = lane; k < WIN; k += 32) {
        dot = fmaf(__ldg(nr + k), w[k], dot);
        wsum += w[k];
    }
    #pragma unroll
    for (int off = 16; off > 0; off >>= 1) {
        dot  += __shfl_down_sync(0xffffffffu, dot, off);
        wsum += __shfl_down_sync(0xffffffffu, wsum, off);
    }
    if (lane == 0) {
        wv_sh[half][row] = dot;
        if (warp == 0) wsum_sh = wsum;
    }
    __syncthreads();

    if (tid < 8) {
        const int f = tid >> 2, i = tid & 3;
        vmax[f][i] = fmax((double)(wv_sh[f][i] / wsum_sh), 0.0);
    }
    __syncthreads();

    if (tid < 18) {
        const int f = tid / 9, j = tid % 9;
        const double s = vmax[f][0] + vmax[f][1] + vmax[f][2] + vmax[f][3];
        double wp = vmax[f][0] * (double)__ldg(basis + 0 + j)
                  + vmax[f][1] * (double)__ldg(basis + 9 + j)
                  + vmax[f][2] * (double)__ldg(basis + 18 + j)
                  + vmax[f][3] * (double)__ldg(basis + 27 + j);
        if (j == 0 || j == 4 || j == 8) wp += 4.0 - s;
        wp_sh[f][j] = wp;
    }
    __syncthreads();

    if (tid < 18) {
        const int f = tid / 9, j = tid % 9;
        const int rr = j / 3, col = j % 3;
        const double inv223 = 1.0 / 223.0;
        double Trow, T2;
        if (col < 2) {
            Trow = wp_sh[f][rr * 3 + col] * inv223;
            T2   = wp_sh[f][2 * 3 + col] * inv223;
        } else {
            Trow = -0.5 * wp_sh[f][rr * 3 + 0] - 0.5 * wp_sh[f][rr * 3 + 1] + wp_sh[f][rr * 3 + 2];
            T2   = -0.5 * wp_sh[f][2 * 3 + 0] - 0.5 * wp_sh[f][2 * 3 + 1] + wp_sh[f][2 * 3 + 2];
        }
        const double Mel = (rr < 2) ? (223.0 * Trow + 111.5 * T2) : T2;
        g_M[(blockIdx.x * 2 + f) * 9 + j] = (float)Mel;
    }
}

// ---------------------------------------------------------------------------
// Kernel 2: per-pixel projective warp + bilinear sample.
// - 3x LDG.64 + 1 predicated LDG.64 per bilinear row; single-bit select
// - validity folded into slot weights; per-thread OOB skip gates all loads
// - warp repacks output through shared -> 24x STG.128
// ---------------------------------------------------------------------------
__global__ __launch_bounds__(512) void vrp_warp_bilinear(const float* __restrict__ x,
                                                         float* __restrict__ out) {
    __shared__ float Ms[9];
    __shared__ __align__(16) float stage[16][96];   // per-warp output staging

    const int l = blockIdx.z;
    const int wyi = threadIdx.y;          // warp id in block (row within tile)
    const int lane = threadIdx.x;
    const int c = blockIdx.x * 32 + lane;
    const int r = blockIdx.y * 16 + wyi;

    if (wyi == 0 && lane < 9) Ms[lane] = g_M[l * 9 + lane];
    __syncthreads();

    const float fc = (float)c, fr = (float)r;
    const float pz = fmaf(Ms[6], fc, fmaf(Ms[7], fr, Ms[8]));
    const float inv = __fdividef(1.f, pz);
    const float sx = fmaf(Ms[0], fc, fmaf(Ms[1], fr, Ms[2])) * inv;
    const float sy = fmaf(Ms[3], fc, fmaf(Ms[4], fr, Ms[5])) * inv;

    const float x0f = floorf(sx), y0f = floorf(sy);
    const float wx = sx - x0f, wy = sy - y0f;
    const float omwx = 1.f - wx, omwy = 1.f - wy;

    // y-side row weights (0 if row invalid; NaN-safe: compares false on NaN)
    const float gyT = (y0f >= 0.f  && y0f <= 223.f) ? omwy : 0.f;
    const float gyB = (y0f >= -1.f && y0f <= 222.f) ? wy   : 0.f;

    // x-side slot weights; slot0 = col xb, slot1 = col xb+1, xb = clamp(x0,0,222)
    const bool pin = (x0f >= 0.f) && (x0f <= 222.f);
    const float h0 = pin ? omwx : ((x0f == -1.f)  ? wx   : 0.f);
    const float h1 = pin ? wx   : ((x0f == 223.f) ? omwx : 0.f);

    const float wT0 = gyT * h0, wT1 = gyT * h1;
    const float wB0 = gyB * h0, wB1 = gyB * h1;

    float acc0 = 0.f, acc1 = 0.f, acc2 = 0.f;

    // Per-thread gate: fully-OOB pixels issue no loads at all (weights >= 0)
    if ((wT0 + wT1 + wB0 + wB1) > 0.f) {
        const int x0 = (int)x0f;                       // weights gate saturation cases
        const int xb = min(max(x0, 0), WW - 2);
        const int y0c = min(max((int)y0f, -1), HH - 1);
        const int yT = max(y0c, 0);
        const int yB = min(y0c + 1, HH - 1);

        const int x3 = 3 * xb;
        const int hx = x3 >> 1;
        const bool b1 = (x3 & 1) != 0;

        const float2* img2 = (const float2*)(x + (size_t)l * FRAME_FLOATS);

        #pragma unroll
        for (int rowi = 0; rowi < 2; ++rowi) {
            const int g = (rowi ? yB : yT) * (WW * CC / 2) + hx;   // *336
            const float w0s = rowi ? wB0 : wT0;
            const float w1s = rowi ? wB1 : wT1;

            const float2 q0 = __ldg(img2 + g);
            const float2 q1 = __ldg(img2 + g + 1);
            const float2 q2 = __ldg(img2 + g + 2);
            float q3x = 0.f;
            if (b1) q3x = __ldg(img2 + min(g + 3, FRAME_F2 - 1)).x;

            const float e0 = b1 ? q0.y : q0.x;
            const float e1 = b1 ? q1.x : q0.y;
            const float e2 = b1 ? q1.y : q1.x;
            const float e3 = b1 ? q2.x : q1.y;
            const float e4 = b1 ? q2.y : q2.x;
            const float e5 = b1 ? q3x  : q2.y;

            acc0 = fmaf(w0s, e0, acc0);
            acc1 = fmaf(w0s, e1, acc1);
            acc2 = fmaf(w0s, e2, acc2);
            acc0 = fmaf(w1s, e3, acc0);
            acc1 = fmaf(w1s, e4, acc1);
            acc2 = fmaf(w1s, e5, acc2);
        }
    }

    // Repack through shared: warp-local, then 24 lanes emit STG.128.
    stage[wyi][lane * 3 + 0] = acc0;
    stage[wyi][lane * 3 + 1] = acc1;
    stage[wyi][lane * 3 + 2] = acc2;
    __syncwarp();

    if (lane < 24) {
        const float4 v = ((const float4*)stage[wyi])[lane];
        float4* obase = (float4*)(out + ((size_t)(l * HH + r) * WW + blockIdx.x * 32) * CC);
        obase[lane] = v;
    }
}

// ---------------------------------------------------------------------------
// Launch: inputs in metadata order: x (f32), noise (f32), warp_basis (f32).
// ---------------------------------------------------------------------------
extern "C" void kernel_launch(void* const* d_in, const int* in_sizes, int n_in,
                              void* d_out, int out_size) {
    const float* x     = (const float*)d_in[0];
    const float* noise = (const float*)d_in[1];
    const float* basis = (const float*)d_in[2];
    float* out = (float*)d_out;

    vrp_matrices<<<LL / 2, 256>>>(noise, basis);

    dim3 block(32, 16, 1);
    dim3 grid(WW / 32, HH / 16, LL);  // 7 x 14 x 256
    vrp_warp_bilinear<<<grid, block>>>(x, out);
}